// round 9
// baseline (speedup 1.0000x reference)
#include <cuda_runtime.h>
#include <math.h>

// Problem constants (fixed by setup_inputs)
#define N_TOT 5000
#define NE    4000
#define NI    1000
#define T_STEPS 1000
#define NBLK  20
#define NTHR  256
#define NWARP (NTHR/32)
#define WUSE  157              // ceil(5000/32) active warps
#define WTOT  160              // spbits stride (zero-padded)

// Model constants, matching the python reference (f32 roundings)
#define GLE 0.08f
#define GLI 0.1f
#define GP0 0.004069f
#define GP1 0.02672f
#define GP2 0.003276f
#define GP3 0.02138f
#define C0F ((float)(2.0/7.0))
#define C1F ((float)(117.0/7.0))
#define C2F ((float)(-23.0/7.0))
#define PIF 3.14159274101257324f   // float32(pi)

// ------- static device scratch (no allocations allowed) -------
__device__ float g_connT[(size_t)N_TOT * N_TOT];        // 100 MB: conn transposed
__device__ unsigned long long g_flag64[2][WUSE];        // (t<<32)|ballot: sync+data one word
__device__ float g_gcol [(size_t)T_STEPS * N_TOT];      // g staged [t][N]
__device__ float g_phcol[(size_t)T_STEPS * N_TOT];      // phase staged [t][N]
__device__ unsigned g_spbits[(size_t)T_STEPS * WTOT];   // spike bits [t][warp] (for post)

__device__ __forceinline__ unsigned long long ld_rlx64(const unsigned long long* p) {
    unsigned long long v;
    asm volatile("ld.relaxed.gpu.b64 %0, [%1];" : "=l"(v) : "l"(p) : "memory");
    return v;
}
__device__ __forceinline__ void st_rlx64(unsigned long long* p, unsigned long long v) {
    asm volatile("st.relaxed.gpu.b64 [%0], %1;" :: "l"(p), "l"(v) : "memory");
}

// ---------------- transpose conn -> connT ----------------
__global__ void snn_transpose(const float* __restrict__ conn) {
    __shared__ float tile[32][33];
    int bx = blockIdx.x * 32, by = blockIdx.y * 32;
    int x = bx + threadIdx.x;
    #pragma unroll
    for (int r = threadIdx.y; r < 32; r += 8) {
        int y = by + r;
        if (x < N_TOT && y < N_TOT)
            tile[r][threadIdx.x] = conn[(size_t)y * N_TOT + x];
    }
    __syncthreads();
    int xo = by + threadIdx.x;
    #pragma unroll
    for (int r = threadIdx.y; r < 32; r += 8) {
        int yo = bx + r;
        if (xo < N_TOT && yo < N_TOT)
            g_connT[(size_t)yo * N_TOT + xo] = tile[threadIdx.x][r];  // connT[j][i] = conn[i][j]
    }
}

// ---------------- init: reset flags + t=0 staged rows ----------------
__global__ void snn_init() {
    int i = blockIdx.x * blockDim.x + threadIdx.x;
    if (i < 2 * WUSE) ((unsigned long long*)g_flag64)[i] = 0ull;  // step 0, empty ballot
    if (i < WTOT) g_spbits[i] = 0u;
    if (i < N_TOT) {
        g_gcol[i]  = 0.0f;
        g_phcol[i] = 0.0f;
    }
}

// ---------------- main persistent simulation kernel ----------------
__global__ void __launch_bounds__(NTHR, 1) snn_main(
    const float* __restrict__ dtp,
    const float* __restrict__ Input)   // [N, T] row-major (original layout!)
{
    const int tid  = threadIdx.x;
    const int b    = blockIdx.x;
    const int lane = tid & 31;
    const int w32  = tid >> 5;
    const int w    = b * NWARP + w32;       // global warp id
    if (w >= WUSE) return;                  // warps 157..159 exit (excluded from barriers)

    const int i = w * 32 + lane;            // owned neuron
    const bool active = (i < N_TOT);
    const bool isE    = (i < NE);
    const int  ii     = active ? i : 0;     // clamp for safe addressing

    const float dt   = *dtp;
    const float tauE = 2.0f;
    const float tauI = 5.0f;

    float ga = 0.0f, gb = 0.0f, gs = 0.0f, phase = 0.0f;
    const float* inrow = Input + (size_t)ii * T_STEPS;

    __shared__ int sList[N_TOT];   // fired list, built on fired steps only

    const float* cT = g_connT;
    const bool has4 = (lane + 128) < WUSE;

    float inp = inrow[1];   // prefetched input for the current step

    for (int t = 1; t < T_STEPS; t++) {
        const int rb = (t - 1) & 1;
        const int wb = t & 1;
        const int tm1 = t - 1;

        // ---- poll all 157 warp-flags (5 coalesced u64 loads per lane) ----
        unsigned long long f0, f1, f2, f3, f4;
        const unsigned long long* F = g_flag64[rb];
        for (;;) {
            f0 = ld_rlx64(&F[lane]);
            f1 = ld_rlx64(&F[lane + 32]);
            f2 = ld_rlx64(&F[lane + 64]);
            f3 = ld_rlx64(&F[lane + 96]);
            f4 = has4 ? ld_rlx64(&F[lane + 128]) : (0x7fffffffull << 32);
            bool ok = (int)(f0 >> 32) >= tm1 && (int)(f1 >> 32) >= tm1 &&
                      (int)(f2 >> 32) >= tm1 && (int)(f3 >> 32) >= tm1 &&
                      (int)(f4 >> 32) >= tm1;
            if (__ballot_sync(0xffffffffu, ok) == 0xffffffffu) break;
        }
        unsigned bb0 = (unsigned)f0, bb1 = (unsigned)f1, bb2 = (unsigned)f2,
                 bb3 = (unsigned)f3, bb4 = (unsigned)f4;

        // ---- Ftot = total spikes at t-1 (popc + butterfly; uniform across warps) ----
        int Ftot = __popc(bb0) + __popc(bb1) + __popc(bb2) + __popc(bb3) + __popc(bb4);
        #pragma unroll
        for (int o = 16; o > 0; o >>= 1)
            Ftot += __shfl_xor_sync(0xffffffffu, Ftot, o);

        // ---- prefetch next step's input early (hide DRAM latency) ----
        float inp_next = 0.0f;
        if (t + 1 < T_STEPS) inp_next = inrow[t + 1];

        // ---- sparse gather (rare path; numeric loop FROZEN from R5) ----
        float sumE = 0.0f, sumI = 0.0f;
        if (Ftot > 0) {
            if (w32 == 0) {
                // warp 0 builds the ascending-j list from its ballot snapshot
                unsigned wbits[5] = { bb0, bb1, bb2, bb3, bb4 };
                int base = 0;
                #pragma unroll
                for (int k = 0; k < 5; k++) {
                    int c = __popc(wbits[k]);
                    int pre = c;
                    #pragma unroll
                    for (int o = 1; o < 32; o <<= 1) {
                        int v = __shfl_up_sync(0xffffffffu, pre, o);
                        if (lane >= o) pre += v;
                    }
                    int off = base + (pre - c);
                    unsigned bits = wbits[k];
                    int jbase = (k * 32 + lane) * 32;
                    while (bits) {
                        int l2 = __ffs(bits) - 1;
                        bits &= bits - 1;
                        sList[off++] = jbase + l2;
                    }
                    base += __shfl_sync(0xffffffffu, pre, 31);
                }
            }
            __syncthreads();
            #pragma unroll 16
            for (int m = 0; m < Ftot; m++) {
                int j = sList[m];
                float v = cT[(size_t)j * N_TOT + ii];
                if (j < NE) sumE += v; else sumI += v;   // ascending-j order (bit-identical)
            }
            __syncthreads();   // protect sList for the next fired step
        }

        // ---- pointwise neuron update (verbatim R5 expressions; do not touch) ----
        float c = cosf(phase);
        float s = sinf(phase);
        float one_c = 1.0f + c;
        float ph2;
        if (isE) {
            ga = ga + (-ga / tauE + GP0 * sumE) * dt;
            gb = gb + (-gb / tauE + GP1 * sumI) * dt;
            gs = gs + (-gs / tauE + GP0 * sumE + GP1 * sumI) * dt;
            ph2 = phase + (-GLE * c + C0F * one_c * inp
                           + ga * (C1F * one_c - s) + gb * (C2F * one_c - s)) * dt;
        } else {
            ga = ga + (-ga / tauI + GP2 * sumE) * dt;
            gb = gb + (-gb / tauI + GP3 * sumI) * dt;
            gs = gs + (-gs / tauI + GP2 * sumE + GP3 * sumI) * dt;
            ph2 = phase + (-GLI * c + C0F * one_c * inp
                           + ga * (C1F * one_c - s) + gb * (C2F * one_c - s)) * dt;
        }
        bool fired = active && (ph2 >= PIF);
        if (fired) ph2 = ph2 - 2.0f * PIF;
        phase = ph2;
        inp = inp_next;

        // ---- publish: single relaxed u64 carries step + ballot (no fence needed) ----
        unsigned bal = __ballot_sync(0xffffffffu, fired);
        if (lane == 0) {
            st_rlx64(&g_flag64[wb][w], ((unsigned long long)t << 32) | (unsigned long long)bal);
            g_spbits[(size_t)t * WTOT + w] = bal;
        }

        // ---- coalesced tail stores (read only after kernel completion) ----
        if (active) {
            size_t o = (size_t)t * N_TOT + i;
            g_gcol[o]  = gs;
            g_phcol[o] = ph2;
        }
    }
}

// ---------------- post: [t][N] staging -> [N][T] outputs, V = theta2V ----------
__global__ void snn_post(float* __restrict__ Vout, float* __restrict__ gout,
                         float* __restrict__ spkout) {
    __shared__ float tp[32][33], tg[32][33], ts[32][33];
    int t0 = blockIdx.x * 32, n0 = blockIdx.y * 32;
    int n = n0 + threadIdx.x;
    #pragma unroll
    for (int ty = threadIdx.y; ty < 32; ty += 8) {
        int t = t0 + ty;
        if (t < T_STEPS && n < N_TOT) {
            size_t o = (size_t)t * N_TOT + n;
            tp[ty][threadIdx.x] = g_phcol[o];
            tg[ty][threadIdx.x] = g_gcol[o];
            unsigned bits = g_spbits[(size_t)t * WTOT + (n >> 5)];
            ts[ty][threadIdx.x] = ((bits >> (n & 31)) & 1u) ? 1.0f : 0.0f;
        }
    }
    __syncthreads();
    int t = t0 + threadIdx.x;
    #pragma unroll
    for (int ny = threadIdx.y; ny < 32; ny += 8) {
        int nn = n0 + ny;
        if (t < T_STEPS && nn < N_TOT) {
            size_t o = (size_t)nn * T_STEPS + t;
            Vout[o]   = -58.5f + 3.5f * tanf(0.5f * tp[threadIdx.x][ny]);
            gout[o]   = tg[threadIdx.x][ny];
            spkout[o] = ts[threadIdx.x][ny];
        }
    }
}

// ---------------- finalize: Out[t] = (g_gcol[t] . W) / N ----------------
__global__ void snn_finalize(const float* __restrict__ W, float* __restrict__ Out) {
    const int t = blockIdx.x;
    const int tid = threadIdx.x;
    __shared__ float sred[8];
    float acc = 0.0f;
    if (t > 0) {
        const float* gr = &g_gcol[(size_t)t * N_TOT];
        for (int n = tid; n < N_TOT; n += 256) acc += gr[n] * W[n];
    }
    #pragma unroll
    for (int off = 16; off > 0; off >>= 1) acc += __shfl_down_sync(0xffffffffu, acc, off);
    if ((tid & 31) == 0) sred[tid >> 5] = acc;
    __syncthreads();
    if (tid == 0) {
        float sm = 0.0f;
        #pragma unroll
        for (int ww = 0; ww < 8; ww++) sm += sred[ww];
        Out[t] = sm / 5000.0f;
    }
}

extern "C" void kernel_launch(void* const* d_in, const int* in_sizes, int n_in,
                              void* d_out, int out_size) {
    const float* dt    = (const float*)d_in[0];
    const float* Input = (const float*)d_in[1];
    const float* conn  = (const float*)d_in[2];
    const float* Wout  = (const float*)d_in[3];

    float* out = (float*)d_out;
    float* Out  = out;                       // [T]
    float* Vout = out + T_STEPS;             // [N, T]
    float* gout = Vout + (size_t)N_TOT * T_STEPS;
    float* spkout = gout + (size_t)N_TOT * T_STEPS;

    {
        dim3 g((N_TOT + 31) / 32, (N_TOT + 31) / 32);
        snn_transpose<<<g, dim3(32, 8)>>>(conn);
    }
    snn_init<<<(N_TOT + 255) / 256, 256>>>();
    snn_main<<<NBLK, NTHR>>>(dt, Input);
    {
        dim3 g((T_STEPS + 31) / 32, (N_TOT + 31) / 32);
        snn_post<<<g, dim3(32, 8)>>>(Vout, gout, spkout);
    }
    snn_finalize<<<T_STEPS, 256>>>(Wout, Out);
}

// round 12
// speedup vs baseline: 1.0589x; 1.0589x over previous
#include <cuda_runtime.h>
#include <math.h>

// Problem constants (fixed by setup_inputs)
#define N_TOT 5000
#define NE    4000
#define NI    1000
#define T_STEPS 1000
#define NBLK  20
#define NTHR  256
#define NWARP (NTHR/32)
#define WTOT  160              // warps total = spbits stride

// Model constants, matching the python reference (f32 roundings)
#define GLE 0.08f
#define GLI 0.1f
#define GP0 0.004069f
#define GP1 0.02672f
#define GP2 0.003276f
#define GP3 0.02138f
#define C0F ((float)(2.0/7.0))
#define C1F ((float)(117.0/7.0))
#define C2F ((float)(-23.0/7.0))
#define PIF 3.14159274101257324f   // float32(pi)

// ------- static device scratch (no allocations allowed) -------
__device__ float g_connT[(size_t)N_TOT * N_TOT];        // 100 MB: conn transposed
__device__ int   g_flag[2][NBLK];                       // packed: (t<<9)|blockSpikeCount
__device__ float g_gcol [(size_t)T_STEPS * N_TOT];      // g staged [t][N]
__device__ float g_phcol[(size_t)T_STEPS * N_TOT];      // phase staged [t][N]
__device__ unsigned g_spbits[(size_t)T_STEPS * WTOT];   // spike ballots [t][warp]

__device__ __forceinline__ int ld_acquire_gpu(const int* p) {
    int v;
    asm volatile("ld.acquire.gpu.b32 %0, [%1];" : "=r"(v) : "l"(p) : "memory");
    return v;
}
__device__ __forceinline__ void st_relaxed_gpu(int* p, int v) {
    asm volatile("st.relaxed.gpu.b32 [%0], %1;" :: "l"(p), "r"(v) : "memory");
}

// ---------------- transpose conn -> connT ----------------
__global__ void snn_transpose(const float* __restrict__ conn) {
    __shared__ float tile[32][33];
    int bx = blockIdx.x * 32, by = blockIdx.y * 32;
    int x = bx + threadIdx.x;
    #pragma unroll
    for (int r = threadIdx.y; r < 32; r += 8) {
        int y = by + r;
        if (x < N_TOT && y < N_TOT)
            tile[r][threadIdx.x] = conn[(size_t)y * N_TOT + x];
    }
    __syncthreads();
    int xo = by + threadIdx.x;
    #pragma unroll
    for (int r = threadIdx.y; r < 32; r += 8) {
        int yo = bx + r;
        if (xo < N_TOT && yo < N_TOT)
            g_connT[(size_t)yo * N_TOT + xo] = tile[threadIdx.x][r];  // connT[j][i] = conn[i][j]
    }
}

// ---------------- init: reset flags + t=0 staged rows ----------------
__global__ void snn_init() {
    int i = blockIdx.x * blockDim.x + threadIdx.x;
    if (i < 2 * NBLK) ((int*)g_flag)[i] = 0;   // step 0, cnt 0
    if (i < WTOT) g_spbits[i] = 0u;
    if (i < N_TOT) {
        g_gcol[i]  = 0.0f;
        g_phcol[i] = 0.0f;
    }
}

// ---------------- main persistent simulation kernel ----------------
__global__ void __launch_bounds__(NTHR, 1) snn_main(
    const float* __restrict__ dtp,
    const float* __restrict__ Input)   // [N, T] row-major
{
    const int tid  = threadIdx.x;
    const int b    = blockIdx.x;
    const int i    = b * NTHR + tid;
    const bool active = (i < N_TOT);
    const bool isE    = (i < NE);
    const int  ii     = active ? i : 0;     // clamp for safe addressing
    const int  lane   = tid & 31;
    const int  w32    = tid >> 5;
    const int  w      = b * NWARP + w32;    // global warp id (matches i>>5 for active i)

    const float dt   = *dtp;
    const float tauE = 2.0f;
    const float tauI = 5.0f;

    float ga = 0.0f, gb = 0.0f, gs = 0.0f, phase = 0.0f;
    const float* inrow = Input + (size_t)ii * T_STEPS;

    __shared__ int      sList[N_TOT];   // fired list (fired steps only)
    __shared__ unsigned sBits[WTOT];    // staged ballots (fired steps only)
    __shared__ int      sWcnt[NWARP];   // producer-side per-warp counts

    const float* cT = g_connT;

    float inp = inrow[1];   // prefetched input for the current step

    for (int t = 1; t < T_STEPS; t++) {
        const int rb = (t - 1) & 1;
        const int wb = t & 1;
        const int tm1 = t - 1;

        // ---- every warp polls the 20-flag line itself (one coalesced acquire) ----
        int cnt = 0;
        if (lane < NBLK) {
            int v;
            do { v = ld_acquire_gpu(&g_flag[rb][lane]); } while ((v >> 9) < tm1);
            cnt = v & 511;
        }
        int Ftot = cnt;
        #pragma unroll
        for (int o = 16; o > 0; o >>= 1)
            Ftot += __shfl_xor_sync(0xffffffffu, Ftot, o);

        // ---- prefetch next step's input early (hide DRAM latency) ----
        float inp_next = 0.0f;
        if (t + 1 < T_STEPS) inp_next = inrow[t + 1];

        // ---- sparse gather (rare path; numeric loop FROZEN) ----
        float sumE = 0.0f, sumI = 0.0f;
        if (Ftot > 0) {
            if (tid < WTOT)
                sBits[tid] = (unsigned)__ldcg((const int*)&g_spbits[(size_t)tm1 * WTOT + tid]);
            __syncthreads();
            if (w32 == 0) {
                // warp 0 builds the ascending-j fired list (R9-validated build)
                unsigned wbits[5];
                #pragma unroll
                for (int k = 0; k < 5; k++) wbits[k] = sBits[k * 32 + lane];
                int base = 0;
                #pragma unroll
                for (int k = 0; k < 5; k++) {
                    int c = __popc(wbits[k]);
                    int pre = c;
                    #pragma unroll
                    for (int o = 1; o < 32; o <<= 1) {
                        int v = __shfl_up_sync(0xffffffffu, pre, o);
                        if (lane >= o) pre += v;
                    }
                    int off = base + (pre - c);
                    unsigned bits = wbits[k];
                    int jbase = (k * 32 + lane) * 32;
                    while (bits) {
                        int l2 = __ffs(bits) - 1;
                        bits &= bits - 1;
                        sList[off++] = jbase + l2;
                    }
                    base += __shfl_sync(0xffffffffu, pre, 31);
                }
            }
            __syncthreads();
            #pragma unroll 16
            for (int m = 0; m < Ftot; m++) {
                int j = sList[m];
                float v = cT[(size_t)j * N_TOT + ii];
                if (j < NE) sumE += v; else sumI += v;   // ascending-j (bit-identical)
            }
            __syncthreads();   // protect sList/sBits for the next fired step
        }

        // ---- pointwise neuron update (FROZEN expressions; do not touch) ----
        float c = cosf(phase);
        float s = sinf(phase);
        float one_c = 1.0f + c;
        float ph2;
        if (isE) {
            ga = ga + (-ga / tauE + GP0 * sumE) * dt;
            gb = gb + (-gb / tauE + GP1 * sumI) * dt;
            gs = gs + (-gs / tauE + GP0 * sumE + GP1 * sumI) * dt;
            ph2 = phase + (-GLE * c + C0F * one_c * inp
                           + ga * (C1F * one_c - s) + gb * (C2F * one_c - s)) * dt;
        } else {
            ga = ga + (-ga / tauI + GP2 * sumE) * dt;
            gb = gb + (-gb / tauI + GP3 * sumI) * dt;
            gs = gs + (-gs / tauI + GP2 * sumE + GP3 * sumI) * dt;
            ph2 = phase + (-GLI * c + C0F * one_c * inp
                           + ga * (C1F * one_c - s) + gb * (C2F * one_c - s)) * dt;
        }
        bool fired = active && (ph2 >= PIF);
        if (fired) ph2 = ph2 - 2.0f * PIF;
        phase = ph2;
        inp = inp_next;

        // ---- publish: ballot word per warp + count-carrying block flag ----
        unsigned bal = __ballot_sync(0xffffffffu, fired);
        if (lane == 0) {
            sWcnt[w32] = __popc(bal);
            g_spbits[(size_t)t * WTOT + w] = bal;
        }
        __syncthreads();                // B2: counts + ballot stores ordered in-CTA

        int cTt = 0;
        #pragma unroll
        for (int ww = 0; ww < NWARP; ww++) cTt += sWcnt[ww];
        if (cTt > 0) {                  // block-uniform (R5's proven fence pattern)
            if (fired) __threadfence();
            __syncthreads();
        }
        if (tid == 0) st_relaxed_gpu(&g_flag[wb][b], (t << 9) | cTt);

        // ---- coalesced tail stores (read only after kernel completion) ----
        if (active) {
            size_t o = (size_t)t * N_TOT + i;
            g_gcol[o]  = gs;
            g_phcol[o] = ph2;
        }
    }
}

// ---------------- post: [t][N] staging -> [N][T] outputs, V = theta2V ----------
__global__ void snn_post(float* __restrict__ Vout, float* __restrict__ gout,
                         float* __restrict__ spkout) {
    __shared__ float tp[32][33], tg[32][33], ts[32][33];
    int t0 = blockIdx.x * 32, n0 = blockIdx.y * 32;
    int n = n0 + threadIdx.x;
    #pragma unroll
    for (int ty = threadIdx.y; ty < 32; ty += 8) {
        int t = t0 + ty;
        if (t < T_STEPS && n < N_TOT) {
            size_t o = (size_t)t * N_TOT + n;
            tp[ty][threadIdx.x] = g_phcol[o];
            tg[ty][threadIdx.x] = g_gcol[o];
            unsigned bits = g_spbits[(size_t)t * WTOT + (n >> 5)];
            ts[ty][threadIdx.x] = ((bits >> (n & 31)) & 1u) ? 1.0f : 0.0f;
        }
    }
    __syncthreads();
    int t = t0 + threadIdx.x;
    #pragma unroll
    for (int ny = threadIdx.y; ny < 32; ny += 8) {
        int nn = n0 + ny;
        if (t < T_STEPS && nn < N_TOT) {
            size_t o = (size_t)nn * T_STEPS + t;
            Vout[o]   = -58.5f + 3.5f * tanf(0.5f * tp[threadIdx.x][ny]);
            gout[o]   = tg[threadIdx.x][ny];
            spkout[o] = ts[threadIdx.x][ny];
        }
    }
}

// ---------------- finalize: Out[t] = (g_gcol[t] . W) / N ----------------
__global__ void snn_finalize(const float* __restrict__ W, float* __restrict__ Out) {
    const int t = blockIdx.x;
    const int tid = threadIdx.x;
    __shared__ float sred[8];
    float acc = 0.0f;
    if (t > 0) {
        const float* gr = &g_gcol[(size_t)t * N_TOT];
        for (int n = tid; n < N_TOT; n += 256) acc += gr[n] * W[n];
    }
    #pragma unroll
    for (int off = 16; off > 0; off >>= 1) acc += __shfl_down_sync(0xffffffffu, acc, off);
    if ((tid & 31) == 0) sred[tid >> 5] = acc;
    __syncthreads();
    if (tid == 0) {
        float sm = 0.0f;
        #pragma unroll
        for (int ww = 0; ww < 8; ww++) sm += sred[ww];
        Out[t] = sm / 5000.0f;
    }
}

extern "C" void kernel_launch(void* const* d_in, const int* in_sizes, int n_in,
                              void* d_out, int out_size) {
    const float* dt    = (const float*)d_in[0];
    const float* Input = (const float*)d_in[1];
    const float* conn  = (const float*)d_in[2];
    const float* Wout  = (const float*)d_in[3];

    float* out = (float*)d_out;
    float* Out  = out;                       // [T]
    float* Vout = out + T_STEPS;             // [N, T]
    float* gout = Vout + (size_t)N_TOT * T_STEPS;
    float* spkout = gout + (size_t)N_TOT * T_STEPS;

    {
        dim3 g((N_TOT + 31) / 32, (N_TOT + 31) / 32);
        snn_transpose<<<g, dim3(32, 8)>>>(conn);
    }
    snn_init<<<(N_TOT + 255) / 256, 256>>>();
    snn_main<<<NBLK, NTHR>>>(dt, Input);
    {
        dim3 g((T_STEPS + 31) / 32, (N_TOT + 31) / 32);
        snn_post<<<g, dim3(32, 8)>>>(Vout, gout, spkout);
    }
    snn_finalize<<<T_STEPS, 256>>>(Wout, Out);
}

// round 13
// speedup vs baseline: 2.7432x; 2.5906x over previous
#include <cuda_runtime.h>
#include <math.h>

// Problem constants (fixed by setup_inputs)
#define N_TOT 5000
#define NE    4000
#define NI    1000
#define T_STEPS 1000
#define NBLK  20
#define NTHR  256
#define NWARP (NTHR/32)
#define WTOT  160              // warps total = flag slots = spbits stride

// Model constants, matching the python reference (f32 roundings)
#define GLE 0.08f
#define GLI 0.1f
#define GP0 0.004069f
#define GP1 0.02672f
#define GP2 0.003276f
#define GP3 0.02138f
#define C0F ((float)(2.0/7.0))
#define C1F ((float)(117.0/7.0))
#define C2F ((float)(-23.0/7.0))
#define PIF 3.14159274101257324f   // float32(pi)

// ------- static device scratch (no allocations allowed) -------
__device__ float g_connT[(size_t)N_TOT * N_TOT];        // 100 MB: conn transposed
__device__ unsigned long long g_flag64[2][WTOT];        // (t<<32)|ballot: sync+data, one word/warp
__device__ float g_gcol [(size_t)T_STEPS * N_TOT];      // g staged [t][N]
__device__ float g_phcol[(size_t)T_STEPS * N_TOT];      // phase staged [t][N]
__device__ unsigned g_spbits[(size_t)T_STEPS * WTOT];   // spike ballots [t][warp] (post only)

__device__ __forceinline__ unsigned long long ld_rlx64(const unsigned long long* p) {
    unsigned long long v;
    asm volatile("ld.relaxed.gpu.b64 %0, [%1];" : "=l"(v) : "l"(p) : "memory");
    return v;
}
__device__ __forceinline__ void st_rlx64(unsigned long long* p, unsigned long long v) {
    asm volatile("st.relaxed.gpu.b64 [%0], %1;" :: "l"(p), "l"(v) : "memory");
}

// ---------------- transpose conn -> connT ----------------
__global__ void snn_transpose(const float* __restrict__ conn) {
    __shared__ float tile[32][33];
    int bx = blockIdx.x * 32, by = blockIdx.y * 32;
    int x = bx + threadIdx.x;
    #pragma unroll
    for (int r = threadIdx.y; r < 32; r += 8) {
        int y = by + r;
        if (x < N_TOT && y < N_TOT)
            tile[r][threadIdx.x] = conn[(size_t)y * N_TOT + x];
    }
    __syncthreads();
    int xo = by + threadIdx.x;
    #pragma unroll
    for (int r = threadIdx.y; r < 32; r += 8) {
        int yo = bx + r;
        if (xo < N_TOT && yo < N_TOT)
            g_connT[(size_t)yo * N_TOT + xo] = tile[threadIdx.x][r];  // connT[j][i] = conn[i][j]
    }
}

// ---------------- init: reset flags + t=0 staged rows ----------------
__global__ void snn_init() {
    int i = blockIdx.x * blockDim.x + threadIdx.x;
    if (i < 2 * WTOT) ((unsigned long long*)g_flag64)[i] = 0ull;  // step 0, empty ballots
    if (i < WTOT) g_spbits[i] = 0u;
    if (i < N_TOT) {
        g_gcol[i]  = 0.0f;
        g_phcol[i] = 0.0f;
    }
}

// ---------------- main persistent simulation kernel ----------------
__global__ void __launch_bounds__(NTHR, 1) snn_main(
    const float* __restrict__ dtp,
    const float* __restrict__ Input)   // [N, T] row-major
{
    const int tid  = threadIdx.x;
    const int b    = blockIdx.x;
    const int i    = b * NTHR + tid;
    const bool active = (i < N_TOT);
    const bool isE    = (i < NE);
    const int  ii     = active ? i : 0;     // clamp for safe addressing
    const int  lane   = tid & 31;
    const int  w32    = tid >> 5;
    const int  w      = b * NWARP + w32;    // global warp id

    const float dt   = *dtp;
    const float tauE = 2.0f;
    const float tauI = 5.0f;

    float ga = 0.0f, gb = 0.0f, gs = 0.0f, phase = 0.0f;
    const float* inrow = Input + (size_t)ii * T_STEPS;

    __shared__ int      sList[N_TOT];   // fired list (fired steps only)
    __shared__ unsigned sBits[WTOT];    // ballots staged by the polling warp
    __shared__ int      sF;             // Ftot broadcast

    const float* cT = g_connT;

    float inp = inrow[1];   // prefetched input for the current step

    for (int t = 1; t < T_STEPS; t++) {
        const int rb = (t - 1) & 1;
        const int wb = t & 1;
        const int tm1 = t - 1;

        // ---- ONLY warp 0 polls: 5 coalesced u64 loads cover all 160 flags ----
        if (w32 == 0) {
            const unsigned long long* F = g_flag64[rb];
            unsigned long long f0, f1, f2, f3, f4;
            for (;;) {
                f0 = ld_rlx64(&F[lane]);
                f1 = ld_rlx64(&F[lane + 32]);
                f2 = ld_rlx64(&F[lane + 64]);
                f3 = ld_rlx64(&F[lane + 96]);
                f4 = ld_rlx64(&F[lane + 128]);
                bool ok = (int)(f0 >> 32) >= tm1 && (int)(f1 >> 32) >= tm1 &&
                          (int)(f2 >> 32) >= tm1 && (int)(f3 >> 32) >= tm1 &&
                          (int)(f4 >> 32) >= tm1;
                if (__ballot_sync(0xffffffffu, ok) == 0xffffffffu) break;
            }
            sBits[lane]       = (unsigned)f0;
            sBits[lane + 32]  = (unsigned)f1;
            sBits[lane + 64]  = (unsigned)f2;
            sBits[lane + 96]  = (unsigned)f3;
            sBits[lane + 128] = (unsigned)f4;
            int Fl = __popc((unsigned)f0) + __popc((unsigned)f1) + __popc((unsigned)f2)
                   + __popc((unsigned)f3) + __popc((unsigned)f4);
            #pragma unroll
            for (int o = 16; o > 0; o >>= 1)
                Fl += __shfl_xor_sync(0xffffffffu, Fl, o);
            if (lane == 0) sF = Fl;
        }
        __syncthreads();                 // B1: broadcast Ftot + staged ballots
        const int Ftot = sF;

        // ---- prefetch next step's input early (hide DRAM latency) ----
        float inp_next = 0.0f;
        if (t + 1 < T_STEPS) inp_next = inrow[t + 1];

        // ---- sparse gather (rare path; numeric loop FROZEN) ----
        float sumE = 0.0f, sumI = 0.0f;
        if (Ftot > 0) {
            if (w32 == 0) {
                // warp 0 builds the ascending-j fired list (R12-validated build)
                unsigned wbits[5];
                #pragma unroll
                for (int k = 0; k < 5; k++) wbits[k] = sBits[k * 32 + lane];
                int base = 0;
                #pragma unroll
                for (int k = 0; k < 5; k++) {
                    int c = __popc(wbits[k]);
                    int pre = c;
                    #pragma unroll
                    for (int o = 1; o < 32; o <<= 1) {
                        int v = __shfl_up_sync(0xffffffffu, pre, o);
                        if (lane >= o) pre += v;
                    }
                    int off = base + (pre - c);
                    unsigned bits = wbits[k];
                    int jbase = (k * 32 + lane) * 32;
                    while (bits) {
                        int l2 = __ffs(bits) - 1;
                        bits &= bits - 1;
                        sList[off++] = jbase + l2;
                    }
                    base += __shfl_sync(0xffffffffu, pre, 31);
                }
            }
            __syncthreads();
            #pragma unroll 16
            for (int m = 0; m < Ftot; m++) {
                int j = sList[m];
                float v = cT[(size_t)j * N_TOT + ii];
                if (j < NE) sumE += v; else sumI += v;   // ascending-j (bit-identical)
            }
            __syncthreads();   // protect sList/sBits for the next fired step
        }

        // ---- pointwise neuron update (FROZEN expressions; do not touch) ----
        float c = cosf(phase);
        float s = sinf(phase);
        float one_c = 1.0f + c;
        float ph2;
        if (isE) {
            ga = ga + (-ga / tauE + GP0 * sumE) * dt;
            gb = gb + (-gb / tauE + GP1 * sumI) * dt;
            gs = gs + (-gs / tauE + GP0 * sumE + GP1 * sumI) * dt;
            ph2 = phase + (-GLE * c + C0F * one_c * inp
                           + ga * (C1F * one_c - s) + gb * (C2F * one_c - s)) * dt;
        } else {
            ga = ga + (-ga / tauI + GP2 * sumE) * dt;
            gb = gb + (-gb / tauI + GP3 * sumI) * dt;
            gs = gs + (-gs / tauI + GP2 * sumE + GP3 * sumI) * dt;
            ph2 = phase + (-GLI * c + C0F * one_c * inp
                           + ga * (C1F * one_c - s) + gb * (C2F * one_c - s)) * dt;
        }
        bool fired = active && (ph2 >= PIF);
        if (fired) ph2 = ph2 - 2.0f * PIF;
        phase = ph2;
        inp = inp_next;

        // ---- publish: one relaxed u64 per warp — no barrier, no fence needed ----
        unsigned bal = __ballot_sync(0xffffffffu, fired);
        if (lane == 0) {
            st_rlx64(&g_flag64[wb][w], ((unsigned long long)t << 32) | (unsigned long long)bal);
            g_spbits[(size_t)t * WTOT + w] = bal;   // post-kernel consumption only
        }

        // ---- coalesced tail stores (read only after kernel completion) ----
        if (active) {
            size_t o = (size_t)t * N_TOT + i;
            g_gcol[o]  = gs;
            g_phcol[o] = ph2;
        }
    }
}

// ---------------- post: [t][N] staging -> [N][T] outputs, V = theta2V ----------
__global__ void snn_post(float* __restrict__ Vout, float* __restrict__ gout,
                         float* __restrict__ spkout) {
    __shared__ float tp[32][33], tg[32][33], ts[32][33];
    int t0 = blockIdx.x * 32, n0 = blockIdx.y * 32;
    int n = n0 + threadIdx.x;
    #pragma unroll
    for (int ty = threadIdx.y; ty < 32; ty += 8) {
        int t = t0 + ty;
        if (t < T_STEPS && n < N_TOT) {
            size_t o = (size_t)t * N_TOT + n;
            tp[ty][threadIdx.x] = g_phcol[o];
            tg[ty][threadIdx.x] = g_gcol[o];
            unsigned bits = g_spbits[(size_t)t * WTOT + (n >> 5)];
            ts[ty][threadIdx.x] = ((bits >> (n & 31)) & 1u) ? 1.0f : 0.0f;
        }
    }
    __syncthreads();
    int t = t0 + threadIdx.x;
    #pragma unroll
    for (int ny = threadIdx.y; ny < 32; ny += 8) {
        int nn = n0 + ny;
        if (t < T_STEPS && nn < N_TOT) {
            size_t o = (size_t)nn * T_STEPS + t;
            Vout[o]   = -58.5f + 3.5f * tanf(0.5f * tp[threadIdx.x][ny]);
            gout[o]   = tg[threadIdx.x][ny];
            spkout[o] = ts[threadIdx.x][ny];
        }
    }
}

// ---------------- finalize: Out[t] = (g_gcol[t] . W) / N ----------------
__global__ void snn_finalize(const float* __restrict__ W, float* __restrict__ Out) {
    const int t = blockIdx.x;
    const int tid = threadIdx.x;
    __shared__ float sred[8];
    float acc = 0.0f;
    if (t > 0) {
        const float* gr = &g_gcol[(size_t)t * N_TOT];
        for (int n = tid; n < N_TOT; n += 256) acc += gr[n] * W[n];
    }
    #pragma unroll
    for (int off = 16; off > 0; off >>= 1) acc += __shfl_down_sync(0xffffffffu, acc, off);
    if ((tid & 31) == 0) sred[tid >> 5] = acc;
    __syncthreads();
    if (tid == 0) {
        float sm = 0.0f;
        #pragma unroll
        for (int ww = 0; ww < 8; ww++) sm += sred[ww];
        Out[t] = sm / 5000.0f;
    }
}

extern "C" void kernel_launch(void* const* d_in, const int* in_sizes, int n_in,
                              void* d_out, int out_size) {
    const float* dt    = (const float*)d_in[0];
    const float* Input = (const float*)d_in[1];
    const float* conn  = (const float*)d_in[2];
    const float* Wout  = (const float*)d_in[3];

    float* out = (float*)d_out;
    float* Out  = out;                       // [T]
    float* Vout = out + T_STEPS;             // [N, T]
    float* gout = Vout + (size_t)N_TOT * T_STEPS;
    float* spkout = gout + (size_t)N_TOT * T_STEPS;

    {
        dim3 g((N_TOT + 31) / 32, (N_TOT + 31) / 32);
        snn_transpose<<<g, dim3(32, 8)>>>(conn);
    }
    snn_init<<<(N_TOT + 255) / 256, 256>>>();
    snn_main<<<NBLK, NTHR>>>(dt, Input);
    {
        dim3 g((T_STEPS + 31) / 32, (N_TOT + 31) / 32);
        snn_post<<<g, dim3(32, 8)>>>(Vout, gout, spkout);
    }
    snn_finalize<<<T_STEPS, 256>>>(Wout, Out);
}

// round 14
// speedup vs baseline: 5.9634x; 2.1739x over previous
#include <cuda_runtime.h>
#include <math.h>

// Problem constants (fixed by setup_inputs)
#define N_TOT 5000
#define NE    4000
#define NI    1000
#define T_STEPS 1000
#define NBLK  20
#define NTHR  256
#define NWARP (NTHR/32)
#define WTOT  160              // warps total = flag slots = spbits stride
#define SBLK  40               // speculative kernel blocks
#define STHR  128              // speculative kernel threads

// Model constants, matching the python reference (f32 roundings)
#define GLE 0.08f
#define GLI 0.1f
#define GP0 0.004069f
#define GP1 0.02672f
#define GP2 0.003276f
#define GP3 0.02138f
#define C0F ((float)(2.0/7.0))
#define C1F ((float)(117.0/7.0))
#define C2F ((float)(-23.0/7.0))
#define PIF 3.14159274101257324f   // float32(pi)

// ------- static device scratch (no allocations allowed) -------
__device__ float g_connT[(size_t)N_TOT * N_TOT];        // conn^T (fallback only)
__device__ unsigned long long g_flag64[2][WTOT];        // fallback sync flags
__device__ float g_gcol [(size_t)T_STEPS * N_TOT];      // g staged [t][N]
__device__ float g_phcol[(size_t)T_STEPS * N_TOT];      // phase staged [t][N]
__device__ unsigned g_spbits[(size_t)T_STEPS * WTOT];   // spike ballots [t][warp]
__device__ int g_any;                                   // 1 if any spike fired in speculation
__device__ int g_zeroF;                                 // always 0: opaque Ftot for spec kernel

__device__ __forceinline__ unsigned long long ld_rlx64(const unsigned long long* p) {
    unsigned long long v;
    asm volatile("ld.relaxed.gpu.b64 %0, [%1];" : "=l"(v) : "l"(p) : "memory");
    return v;
}
__device__ __forceinline__ void st_rlx64(unsigned long long* p, unsigned long long v) {
    asm volatile("st.relaxed.gpu.b64 [%0], %1;" :: "l"(p), "l"(v) : "memory");
}
__device__ __forceinline__ int ld_rlx32(const int* p) {
    int v;
    asm volatile("ld.relaxed.gpu.b32 %0, [%1];" : "=r"(v) : "l"(p) : "memory");
    return v;
}

// ---------------- reset: clear speculation flag ----------------
__global__ void snn_reset() { g_any = 0; g_zeroF = 0; }

// ---------------- speculative kernel: no inter-block sync at all ----------------
__global__ void __launch_bounds__(STHR, 1) snn_spec(
    const float* __restrict__ dtp,
    const float* __restrict__ Input)   // [N, T] row-major
{
    const int tid  = threadIdx.x;
    const int b    = blockIdx.x;
    const int i    = b * STHR + tid;
    const bool active = (i < N_TOT);
    const bool isE    = (i < NE);
    const int  ii     = active ? i : 0;
    const int  lane   = tid & 31;
    const int  w32    = tid >> 5;
    const int  w      = b * (STHR / 32) + w32;   // global warp id == i>>5

    const float dt   = *dtp;
    const float tauE = 2.0f;
    const float tauI = 5.0f;

    float ga = 0.0f, gb = 0.0f, gs = 0.0f, phase = 0.0f;
    const float* inrow = Input + (size_t)ii * T_STEPS;

    __shared__ int      sList[N_TOT];   // never-taken gather branch (kept for codegen parity)
    __shared__ unsigned sBits[WTOT];

    const float* cT = g_connT;
    int anyf = 0;

    float inp = inrow[1];   // prefetched input for the current step

    for (int t = 1; t < T_STEPS; t++) {
        // opaque per-iteration load: always 0, but compiler can't unswitch the branch
        const int Ftot = ld_rlx32(&g_zeroF);

        // ---- prefetch next step's input early ----
        float inp_next = 0.0f;
        if (t + 1 < T_STEPS) inp_next = inrow[t + 1];

        // ---- sparse gather (FROZEN text; never executes in speculation) ----
        float sumE = 0.0f, sumI = 0.0f;
        if (Ftot > 0) {
            if (tid < WTOT)
                sBits[tid] = (unsigned)__ldcg((const int*)&g_spbits[(size_t)(t - 1) * WTOT + tid]);
            __syncthreads();
            if (w32 == 0) {
                unsigned wbits[5];
                #pragma unroll
                for (int k = 0; k < 5; k++) wbits[k] = sBits[k * 32 + lane];
                int base = 0;
                #pragma unroll
                for (int k = 0; k < 5; k++) {
                    int c = __popc(wbits[k]);
                    int pre = c;
                    #pragma unroll
                    for (int o = 1; o < 32; o <<= 1) {
                        int v = __shfl_up_sync(0xffffffffu, pre, o);
                        if (lane >= o) pre += v;
                    }
                    int off = base + (pre - c);
                    unsigned bits = wbits[k];
                    int jbase = (k * 32 + lane) * 32;
                    while (bits) {
                        int l2 = __ffs(bits) - 1;
                        bits &= bits - 1;
                        sList[off++] = jbase + l2;
                    }
                    base += __shfl_sync(0xffffffffu, pre, 31);
                }
            }
            __syncthreads();
            #pragma unroll 16
            for (int m = 0; m < Ftot; m++) {
                int j = sList[m];
                float v = cT[(size_t)j * N_TOT + ii];
                if (j < NE) sumE += v; else sumI += v;
            }
            __syncthreads();
        }

        // ---- pointwise neuron update (FROZEN expressions; do not touch) ----
        float c = cosf(phase);
        float s = sinf(phase);
        float one_c = 1.0f + c;
        float ph2;
        if (isE) {
            ga = ga + (-ga / tauE + GP0 * sumE) * dt;
            gb = gb + (-gb / tauE + GP1 * sumI) * dt;
            gs = gs + (-gs / tauE + GP0 * sumE + GP1 * sumI) * dt;
            ph2 = phase + (-GLE * c + C0F * one_c * inp
                           + ga * (C1F * one_c - s) + gb * (C2F * one_c - s)) * dt;
        } else {
            ga = ga + (-ga / tauI + GP2 * sumE) * dt;
            gb = gb + (-gb / tauI + GP3 * sumI) * dt;
            gs = gs + (-gs / tauI + GP2 * sumE + GP3 * sumI) * dt;
            ph2 = phase + (-GLI * c + C0F * one_c * inp
                           + ga * (C1F * one_c - s) + gb * (C2F * one_c - s)) * dt;
        }
        bool fired = active && (ph2 >= PIF);
        if (fired) ph2 = ph2 - 2.0f * PIF;
        phase = ph2;
        inp = inp_next;

        // ---- record ballots + staging (no cross-block communication) ----
        unsigned bal = __ballot_sync(0xffffffffu, fired);
        anyf |= (int)bal;
        if (lane == 0) g_spbits[(size_t)t * WTOT + w] = bal;
        if (active) {
            size_t o = (size_t)t * N_TOT + i;
            g_gcol[o]  = gs;
            g_phcol[o] = ph2;
        }
    }

    // did ANY spike occur? (if yes, speculation invalid past that point -> fallback)
    if (lane == 0 && anyf) atomicExch(&g_any, 1);
}

// ---------------- transpose conn -> connT (fallback only) ----------------
__global__ void snn_transpose(const float* __restrict__ conn) {
    if (g_any == 0) return;
    __shared__ float tile[32][33];
    int bx = blockIdx.x * 32, by = blockIdx.y * 32;
    int x = bx + threadIdx.x;
    #pragma unroll
    for (int r = threadIdx.y; r < 32; r += 8) {
        int y = by + r;
        if (x < N_TOT && y < N_TOT)
            tile[r][threadIdx.x] = conn[(size_t)y * N_TOT + x];
    }
    __syncthreads();
    int xo = by + threadIdx.x;
    #pragma unroll
    for (int r = threadIdx.y; r < 32; r += 8) {
        int yo = bx + r;
        if (xo < N_TOT && yo < N_TOT)
            g_connT[(size_t)yo * N_TOT + xo] = tile[threadIdx.x][r];
    }
}

// ---------------- init: t=0 rows always; fallback flags ----------------
__global__ void snn_init() {
    int i = blockIdx.x * blockDim.x + threadIdx.x;
    if (i < 2 * WTOT) ((unsigned long long*)g_flag64)[i] = 0ull;
    if (i < WTOT) g_spbits[i] = 0u;
    if (i < N_TOT) {
        g_gcol[i]  = 0.0f;
        g_phcol[i] = 0.0f;
    }
}

// ---------------- fallback: synchronized simulation (R13, gated) ----------------
__global__ void __launch_bounds__(NTHR, 1) snn_main(
    const float* __restrict__ dtp,
    const float* __restrict__ Input)
{
    if (g_any == 0) return;   // speculation was exact

    const int tid  = threadIdx.x;
    const int b    = blockIdx.x;
    const int i    = b * NTHR + tid;
    const bool active = (i < N_TOT);
    const bool isE    = (i < NE);
    const int  ii     = active ? i : 0;
    const int  lane   = tid & 31;
    const int  w32    = tid >> 5;
    const int  w      = b * NWARP + w32;

    const float dt   = *dtp;
    const float tauE = 2.0f;
    const float tauI = 5.0f;

    float ga = 0.0f, gb = 0.0f, gs = 0.0f, phase = 0.0f;
    const float* inrow = Input + (size_t)ii * T_STEPS;

    __shared__ int      sList[N_TOT];
    __shared__ unsigned sBits[WTOT];
    __shared__ int      sF;

    const float* cT = g_connT;

    float inp = inrow[1];

    for (int t = 1; t < T_STEPS; t++) {
        const int rb = (t - 1) & 1;
        const int wb = t & 1;
        const int tm1 = t - 1;

        if (w32 == 0) {
            const unsigned long long* F = g_flag64[rb];
            unsigned long long f0, f1, f2, f3, f4;
            for (;;) {
                f0 = ld_rlx64(&F[lane]);
                f1 = ld_rlx64(&F[lane + 32]);
                f2 = ld_rlx64(&F[lane + 64]);
                f3 = ld_rlx64(&F[lane + 96]);
                f4 = ld_rlx64(&F[lane + 128]);
                bool ok = (int)(f0 >> 32) >= tm1 && (int)(f1 >> 32) >= tm1 &&
                          (int)(f2 >> 32) >= tm1 && (int)(f3 >> 32) >= tm1 &&
                          (int)(f4 >> 32) >= tm1;
                if (__ballot_sync(0xffffffffu, ok) == 0xffffffffu) break;
            }
            sBits[lane]       = (unsigned)f0;
            sBits[lane + 32]  = (unsigned)f1;
            sBits[lane + 64]  = (unsigned)f2;
            sBits[lane + 96]  = (unsigned)f3;
            sBits[lane + 128] = (unsigned)f4;
            int Fl = __popc((unsigned)f0) + __popc((unsigned)f1) + __popc((unsigned)f2)
                   + __popc((unsigned)f3) + __popc((unsigned)f4);
            #pragma unroll
            for (int o = 16; o > 0; o >>= 1)
                Fl += __shfl_xor_sync(0xffffffffu, Fl, o);
            if (lane == 0) sF = Fl;
        }
        __syncthreads();
        const int Ftot = sF;

        float inp_next = 0.0f;
        if (t + 1 < T_STEPS) inp_next = inrow[t + 1];

        float sumE = 0.0f, sumI = 0.0f;
        if (Ftot > 0) {
            if (w32 == 0) {
                unsigned wbits[5];
                #pragma unroll
                for (int k = 0; k < 5; k++) wbits[k] = sBits[k * 32 + lane];
                int base = 0;
                #pragma unroll
                for (int k = 0; k < 5; k++) {
                    int c = __popc(wbits[k]);
                    int pre = c;
                    #pragma unroll
                    for (int o = 1; o < 32; o <<= 1) {
                        int v = __shfl_up_sync(0xffffffffu, pre, o);
                        if (lane >= o) pre += v;
                    }
                    int off = base + (pre - c);
                    unsigned bits = wbits[k];
                    int jbase = (k * 32 + lane) * 32;
                    while (bits) {
                        int l2 = __ffs(bits) - 1;
                        bits &= bits - 1;
                        sList[off++] = jbase + l2;
                    }
                    base += __shfl_sync(0xffffffffu, pre, 31);
                }
            }
            __syncthreads();
            #pragma unroll 16
            for (int m = 0; m < Ftot; m++) {
                int j = sList[m];
                float v = cT[(size_t)j * N_TOT + ii];
                if (j < NE) sumE += v; else sumI += v;
            }
            __syncthreads();
        }

        float c = cosf(phase);
        float s = sinf(phase);
        float one_c = 1.0f + c;
        float ph2;
        if (isE) {
            ga = ga + (-ga / tauE + GP0 * sumE) * dt;
            gb = gb + (-gb / tauE + GP1 * sumI) * dt;
            gs = gs + (-gs / tauE + GP0 * sumE + GP1 * sumI) * dt;
            ph2 = phase + (-GLE * c + C0F * one_c * inp
                           + ga * (C1F * one_c - s) + gb * (C2F * one_c - s)) * dt;
        } else {
            ga = ga + (-ga / tauI + GP2 * sumE) * dt;
            gb = gb + (-gb / tauI + GP3 * sumI) * dt;
            gs = gs + (-gs / tauI + GP2 * sumE + GP3 * sumI) * dt;
            ph2 = phase + (-GLI * c + C0F * one_c * inp
                           + ga * (C1F * one_c - s) + gb * (C2F * one_c - s)) * dt;
        }
        bool fired = active && (ph2 >= PIF);
        if (fired) ph2 = ph2 - 2.0f * PIF;
        phase = ph2;
        inp = inp_next;

        unsigned bal = __ballot_sync(0xffffffffu, fired);
        if (lane == 0) {
            st_rlx64(&g_flag64[wb][w], ((unsigned long long)t << 32) | (unsigned long long)bal);
            g_spbits[(size_t)t * WTOT + w] = bal;
        }

        if (active) {
            size_t o = (size_t)t * N_TOT + i;
            g_gcol[o]  = gs;
            g_phcol[o] = ph2;
        }
    }
}

// ---------------- post: [t][N] staging -> [N][T] outputs, V = theta2V ----------
__global__ void snn_post(float* __restrict__ Vout, float* __restrict__ gout,
                         float* __restrict__ spkout) {
    __shared__ float tp[32][33], tg[32][33], ts[32][33];
    int t0 = blockIdx.x * 32, n0 = blockIdx.y * 32;
    int n = n0 + threadIdx.x;
    #pragma unroll
    for (int ty = threadIdx.y; ty < 32; ty += 8) {
        int t = t0 + ty;
        if (t < T_STEPS && n < N_TOT) {
            size_t o = (size_t)t * N_TOT + n;
            tp[ty][threadIdx.x] = g_phcol[o];
            tg[ty][threadIdx.x] = g_gcol[o];
            unsigned bits = g_spbits[(size_t)t * WTOT + (n >> 5)];
            ts[ty][threadIdx.x] = ((bits >> (n & 31)) & 1u) ? 1.0f : 0.0f;
        }
    }
    __syncthreads();
    int t = t0 + threadIdx.x;
    #pragma unroll
    for (int ny = threadIdx.y; ny < 32; ny += 8) {
        int nn = n0 + ny;
        if (t < T_STEPS && nn < N_TOT) {
            size_t o = (size_t)nn * T_STEPS + t;
            Vout[o]   = -58.5f + 3.5f * tanf(0.5f * tp[threadIdx.x][ny]);
            gout[o]   = tg[threadIdx.x][ny];
            spkout[o] = ts[threadIdx.x][ny];
        }
    }
}

// ---------------- finalize: Out[t] = (g_gcol[t] . W) / N ----------------
__global__ void snn_finalize(const float* __restrict__ W, float* __restrict__ Out) {
    const int t = blockIdx.x;
    const int tid = threadIdx.x;
    __shared__ float sred[8];
    float acc = 0.0f;
    if (t > 0) {
        const float* gr = &g_gcol[(size_t)t * N_TOT];
        for (int n = tid; n < N_TOT; n += 256) acc += gr[n] * W[n];
    }
    #pragma unroll
    for (int off = 16; off > 0; off >>= 1) acc += __shfl_down_sync(0xffffffffu, acc, off);
    if ((tid & 31) == 0) sred[tid >> 5] = acc;
    __syncthreads();
    if (tid == 0) {
        float sm = 0.0f;
        #pragma unroll
        for (int ww = 0; ww < 8; ww++) sm += sred[ww];
        Out[t] = sm / 5000.0f;
    }
}

extern "C" void kernel_launch(void* const* d_in, const int* in_sizes, int n_in,
                              void* d_out, int out_size) {
    const float* dt    = (const float*)d_in[0];
    const float* Input = (const float*)d_in[1];
    const float* conn  = (const float*)d_in[2];
    const float* Wout  = (const float*)d_in[3];

    float* out = (float*)d_out;
    float* Out  = out;                       // [T]
    float* Vout = out + T_STEPS;             // [N, T]
    float* gout = Vout + (size_t)N_TOT * T_STEPS;
    float* spkout = gout + (size_t)N_TOT * T_STEPS;

    snn_reset<<<1, 1>>>();
    snn_spec<<<SBLK, STHR>>>(dt, Input);                  // sync-free speculation
    {
        dim3 g((N_TOT + 31) / 32, (N_TOT + 31) / 32);
        snn_transpose<<<g, dim3(32, 8)>>>(conn);          // gated: only if spikes occurred
    }
    snn_init<<<(N_TOT + 255) / 256, 256>>>();             // t=0 rows (+ fallback flags)
    snn_main<<<NBLK, NTHR>>>(dt, Input);                  // gated fallback
    {
        dim3 g((T_STEPS + 31) / 32, (N_TOT + 31) / 32);
        snn_post<<<g, dim3(32, 8)>>>(Vout, gout, spkout);
    }
    snn_finalize<<<T_STEPS, 256>>>(Wout, Out);
}

// round 17
// speedup vs baseline: 7.0139x; 1.1762x over previous
#include <cuda_runtime.h>
#include <math.h>

// Problem constants (fixed by setup_inputs)
#define N_TOT 5000
#define NE    4000
#define NI    1000
#define T_STEPS 1000
#define NBLK  20
#define NTHR  256
#define NWARP (NTHR/32)
#define WTOT  160              // warps total = flag slots = spbits stride
#define SBLK  40               // speculative kernel blocks
#define STHR  128              // speculative kernel threads
#define TTILE 157              // ceil(5000/32) transpose tiles per dim

// Model constants, matching the python reference (f32 roundings)
#define GLE 0.08f
#define GLI 0.1f
#define GP0 0.004069f
#define GP1 0.02672f
#define GP2 0.003276f
#define GP3 0.02138f
#define C0F ((float)(2.0/7.0))
#define C1F ((float)(117.0/7.0))
#define C2F ((float)(-23.0/7.0))
#define PIF 3.14159274101257324f   // float32(pi)

// ------- static device scratch (no allocations allowed) -------
__device__ float g_connT[(size_t)N_TOT * N_TOT];        // conn^T (fallback only)
__device__ unsigned long long g_flag64[2][WTOT];        // fallback sync flags
__device__ float g_gcol [(size_t)T_STEPS * N_TOT];      // g staged [t][N]
__device__ float g_phcol[(size_t)T_STEPS * N_TOT];      // phase staged [t][N]
__device__ unsigned g_spbits[(size_t)T_STEPS * WTOT];   // spike ballots [t][warp]
__device__ int g_any;                                   // 1 if any spike fired in speculation
__device__ int g_Fany[T_STEPS];                         // all zeros; opaque-to-compiler Ftot per step

__device__ __forceinline__ unsigned long long ld_rlx64(const unsigned long long* p) {
    unsigned long long v;
    asm volatile("ld.relaxed.gpu.b64 %0, [%1];" : "=l"(v) : "l"(p) : "memory");
    return v;
}
__device__ __forceinline__ void st_rlx64(unsigned long long* p, unsigned long long v) {
    asm volatile("st.relaxed.gpu.b64 [%0], %1;" :: "l"(p), "l"(v) : "memory");
}

// ---------------- reset: clear speculation flag + per-step Ftot array ----------------
__global__ void snn_reset() {
    int i = blockIdx.x * blockDim.x + threadIdx.x;
    if (i == 0) g_any = 0;
    if (i < T_STEPS) g_Fany[i] = 0;
}

// ---------------- speculative kernel: no inter-block sync at all ----------------
__global__ void __launch_bounds__(STHR, 1) snn_spec(
    const float* __restrict__ dtp,
    const float* __restrict__ Input)   // [N, T] row-major
{
    const int tid  = threadIdx.x;
    const int b    = blockIdx.x;
    const int i    = b * STHR + tid;
    const bool active = (i < N_TOT);
    const bool isE    = (i < NE);
    const int  ii     = active ? i : 0;
    const int  lane   = tid & 31;
    const int  w32    = tid >> 5;
    const int  w      = b * (STHR / 32) + w32;   // global warp id == i>>5

    const float dt   = *dtp;
    const float tauE = 2.0f;
    const float tauI = 5.0f;

    float ga = 0.0f, gb = 0.0f, gs = 0.0f, phase = 0.0f;
    const float* inrow = Input + (size_t)ii * T_STEPS;

    __shared__ int      sList[N_TOT];   // never-taken gather branch (kept for codegen parity)
    __shared__ unsigned sBits[WTOT];

    const float* cT = g_connT;
    int anyf = 0;

    float inp = inrow[1];   // prefetched input for the current step

    for (int t = 1; t < T_STEPS; t++) {
        // t-indexed load: not hoistable, not unswitchable, but prefetchable + L1-resident
        const int Ftot = g_Fany[t];

        // ---- prefetch next step's input early ----
        float inp_next = 0.0f;
        if (t + 1 < T_STEPS) inp_next = inrow[t + 1];

        // ---- sparse gather (FROZEN text; never executes in speculation) ----
        float sumE = 0.0f, sumI = 0.0f;
        if (Ftot > 0) {
            if (tid < WTOT)
                sBits[tid] = (unsigned)__ldcg((const int*)&g_spbits[(size_t)(t - 1) * WTOT + tid]);
            __syncthreads();
            if (w32 == 0) {
                unsigned wbits[5];
                #pragma unroll
                for (int k = 0; k < 5; k++) wbits[k] = sBits[k * 32 + lane];
                int base = 0;
                #pragma unroll
                for (int k = 0; k < 5; k++) {
                    int c = __popc(wbits[k]);
                    int pre = c;
                    #pragma unroll
                    for (int o = 1; o < 32; o <<= 1) {
                        int v = __shfl_up_sync(0xffffffffu, pre, o);
                        if (lane >= o) pre += v;
                    }
                    int off = base + (pre - c);
                    unsigned bits = wbits[k];
                    int jbase = (k * 32 + lane) * 32;
                    while (bits) {
                        int l2 = __ffs(bits) - 1;
                        bits &= bits - 1;
                        sList[off++] = jbase + l2;
                    }
                    base += __shfl_sync(0xffffffffu, pre, 31);
                }
            }
            __syncthreads();
            #pragma unroll 16
            for (int m = 0; m < Ftot; m++) {
                int j = sList[m];
                float v = cT[(size_t)j * N_TOT + ii];
                if (j < NE) sumE += v; else sumI += v;
            }
            __syncthreads();
        }

        // ---- pointwise neuron update (FROZEN expressions; do not touch) ----
        float c = cosf(phase);
        float s = sinf(phase);
        float one_c = 1.0f + c;
        float ph2;
        if (isE) {
            ga = ga + (-ga / tauE + GP0 * sumE) * dt;
            gb = gb + (-gb / tauE + GP1 * sumI) * dt;
            gs = gs + (-gs / tauE + GP0 * sumE + GP1 * sumI) * dt;
            ph2 = phase + (-GLE * c + C0F * one_c * inp
                           + ga * (C1F * one_c - s) + gb * (C2F * one_c - s)) * dt;
        } else {
            ga = ga + (-ga / tauI + GP2 * sumE) * dt;
            gb = gb + (-gb / tauI + GP3 * sumI) * dt;
            gs = gs + (-gs / tauI + GP2 * sumE + GP3 * sumI) * dt;
            ph2 = phase + (-GLI * c + C0F * one_c * inp
                           + ga * (C1F * one_c - s) + gb * (C2F * one_c - s)) * dt;
        }
        bool fired = active && (ph2 >= PIF);
        if (fired) ph2 = ph2 - 2.0f * PIF;
        phase = ph2;
        inp = inp_next;

        // ---- record ballots + staging (no cross-block communication) ----
        unsigned bal = __ballot_sync(0xffffffffu, fired);
        anyf |= (int)bal;
        if (lane == 0) g_spbits[(size_t)t * WTOT + w] = bal;
        if (active) {
            size_t o = (size_t)t * N_TOT + i;
            g_gcol[o]  = gs;
            g_phcol[o] = ph2;
        }
    }

    // did ANY spike occur? (if yes, speculation invalid past that point -> fallback)
    if (lane == 0 && anyf) atomicExch(&g_any, 1);
}

// ---------------- transpose conn -> connT (fallback only; grid-stride gated) ----
__global__ void snn_transpose(const float* __restrict__ conn) {
    if (g_any == 0) return;   // cheap: only gridDim.x block retires when gated off
    __shared__ float tile[32][33];
    for (int tileId = blockIdx.x; tileId < TTILE * TTILE; tileId += gridDim.x) {
        int bx = (tileId % TTILE) * 32, by = (tileId / TTILE) * 32;
        int x = bx + threadIdx.x;
        #pragma unroll
        for (int r = threadIdx.y; r < 32; r += 8) {
            int y = by + r;
            if (x < N_TOT && y < N_TOT)
                tile[r][threadIdx.x] = conn[(size_t)y * N_TOT + x];
        }
        __syncthreads();
        int xo = by + threadIdx.x;
        #pragma unroll
        for (int r = threadIdx.y; r < 32; r += 8) {
            int yo = bx + r;
            if (xo < N_TOT && yo < N_TOT)
                g_connT[(size_t)yo * N_TOT + xo] = tile[threadIdx.x][r];
        }
        __syncthreads();
    }
}

// ---------------- init: t=0 rows always; fallback flags ----------------
__global__ void snn_init() {
    int i = blockIdx.x * blockDim.x + threadIdx.x;
    if (i < 2 * WTOT) ((unsigned long long*)g_flag64)[i] = 0ull;
    if (i < WTOT) g_spbits[i] = 0u;
    if (i < N_TOT) {
        g_gcol[i]  = 0.0f;
        g_phcol[i] = 0.0f;
    }
}

// ---------------- fallback: synchronized simulation (R13, gated) ----------------
__global__ void __launch_bounds__(NTHR, 1) snn_main(
    const float* __restrict__ dtp,
    const float* __restrict__ Input)
{
    if (g_any == 0) return;   // speculation was exact

    const int tid  = threadIdx.x;
    const int b    = blockIdx.x;
    const int i    = b * NTHR + tid;
    const bool active = (i < N_TOT);
    const bool isE    = (i < NE);
    const int  ii     = active ? i : 0;
    const int  lane   = tid & 31;
    const int  w32    = tid >> 5;
    const int  w      = b * NWARP + w32;

    const float dt   = *dtp;
    const float tauE = 2.0f;
    const float tauI = 5.0f;

    float ga = 0.0f, gb = 0.0f, gs = 0.0f, phase = 0.0f;
    const float* inrow = Input + (size_t)ii * T_STEPS;

    __shared__ int      sList[N_TOT];
    __shared__ unsigned sBits[WTOT];
    __shared__ int      sF;

    const float* cT = g_connT;

    float inp = inrow[1];

    for (int t = 1; t < T_STEPS; t++) {
        const int rb = (t - 1) & 1;
        const int wb = t & 1;
        const int tm1 = t - 1;

        if (w32 == 0) {
            const unsigned long long* F = g_flag64[rb];
            unsigned long long f0, f1, f2, f3, f4;
            for (;;) {
                f0 = ld_rlx64(&F[lane]);
                f1 = ld_rlx64(&F[lane + 32]);
                f2 = ld_rlx64(&F[lane + 64]);
                f3 = ld_rlx64(&F[lane + 96]);
                f4 = ld_rlx64(&F[lane + 128]);
                bool ok = (int)(f0 >> 32) >= tm1 && (int)(f1 >> 32) >= tm1 &&
                          (int)(f2 >> 32) >= tm1 && (int)(f3 >> 32) >= tm1 &&
                          (int)(f4 >> 32) >= tm1;
                if (__ballot_sync(0xffffffffu, ok) == 0xffffffffu) break;
            }
            sBits[lane]       = (unsigned)f0;
            sBits[lane + 32]  = (unsigned)f1;
            sBits[lane + 64]  = (unsigned)f2;
            sBits[lane + 96]  = (unsigned)f3;
            sBits[lane + 128] = (unsigned)f4;
            int Fl = __popc((unsigned)f0) + __popc((unsigned)f1) + __popc((unsigned)f2)
                   + __popc((unsigned)f3) + __popc((unsigned)f4);
            #pragma unroll
            for (int o = 16; o > 0; o >>= 1)
                Fl += __shfl_xor_sync(0xffffffffu, Fl, o);
            if (lane == 0) sF = Fl;
        }
        __syncthreads();
        const int Ftot = sF;

        float inp_next = 0.0f;
        if (t + 1 < T_STEPS) inp_next = inrow[t + 1];

        float sumE = 0.0f, sumI = 0.0f;
        if (Ftot > 0) {
            if (w32 == 0) {
                unsigned wbits[5];
                #pragma unroll
                for (int k = 0; k < 5; k++) wbits[k] = sBits[k * 32 + lane];
                int base = 0;
                #pragma unroll
                for (int k = 0; k < 5; k++) {
                    int c = __popc(wbits[k]);
                    int pre = c;
                    #pragma unroll
                    for (int o = 1; o < 32; o <<= 1) {
                        int v = __shfl_up_sync(0xffffffffu, pre, o);
                        if (lane >= o) pre += v;
                    }
                    int off = base + (pre - c);
                    unsigned bits = wbits[k];
                    int jbase = (k * 32 + lane) * 32;
                    while (bits) {
                        int l2 = __ffs(bits) - 1;
                        bits &= bits - 1;
                        sList[off++] = jbase + l2;
                    }
                    base += __shfl_sync(0xffffffffu, pre, 31);
                }
            }
            __syncthreads();
            #pragma unroll 16
            for (int m = 0; m < Ftot; m++) {
                int j = sList[m];
                float v = cT[(size_t)j * N_TOT + ii];
                if (j < NE) sumE += v; else sumI += v;
            }
            __syncthreads();
        }

        float c = cosf(phase);
        float s = sinf(phase);
        float one_c = 1.0f + c;
        float ph2;
        if (isE) {
            ga = ga + (-ga / tauE + GP0 * sumE) * dt;
            gb = gb + (-gb / tauE + GP1 * sumI) * dt;
            gs = gs + (-gs / tauE + GP0 * sumE + GP1 * sumI) * dt;
            ph2 = phase + (-GLE * c + C0F * one_c * inp
                           + ga * (C1F * one_c - s) + gb * (C2F * one_c - s)) * dt;
        } else {
            ga = ga + (-ga / tauI + GP2 * sumE) * dt;
            gb = gb + (-gb / tauI + GP3 * sumI) * dt;
            gs = gs + (-gs / tauI + GP2 * sumE + GP3 * sumI) * dt;
            ph2 = phase + (-GLI * c + C0F * one_c * inp
                           + ga * (C1F * one_c - s) + gb * (C2F * one_c - s)) * dt;
        }
        bool fired = active && (ph2 >= PIF);
        if (fired) ph2 = ph2 - 2.0f * PIF;
        phase = ph2;
        inp = inp_next;

        unsigned bal = __ballot_sync(0xffffffffu, fired);
        if (lane == 0) {
            st_rlx64(&g_flag64[wb][w], ((unsigned long long)t << 32) | (unsigned long long)bal);
            g_spbits[(size_t)t * WTOT + w] = bal;
        }

        if (active) {
            size_t o = (size_t)t * N_TOT + i;
            g_gcol[o]  = gs;
            g_phcol[o] = ph2;
        }
    }
}

// ---------------- post: [t][N] staging -> [N][T] outputs, V = theta2V ----------
__global__ void snn_post(float* __restrict__ Vout, float* __restrict__ gout,
                         float* __restrict__ spkout) {
    __shared__ float tp[32][33], tg[32][33], ts[32][33];
    int t0 = blockIdx.x * 32, n0 = blockIdx.y * 32;
    int n = n0 + threadIdx.x;
    #pragma unroll
    for (int ty = threadIdx.y; ty < 32; ty += 8) {
        int t = t0 + ty;
        if (t < T_STEPS && n < N_TOT) {
            size_t o = (size_t)t * N_TOT + n;
            tp[ty][threadIdx.x] = g_phcol[o];
            tg[ty][threadIdx.x] = g_gcol[o];
            unsigned bits = g_spbits[(size_t)t * WTOT + (n >> 5)];
            ts[ty][threadIdx.x] = ((bits >> (n & 31)) & 1u) ? 1.0f : 0.0f;
        }
    }
    __syncthreads();
    int t = t0 + threadIdx.x;
    #pragma unroll
    for (int ny = threadIdx.y; ny < 32; ny += 8) {
        int nn = n0 + ny;
        if (t < T_STEPS && nn < N_TOT) {
            size_t o = (size_t)nn * T_STEPS + t;
            Vout[o]   = -58.5f + 3.5f * tanf(0.5f * tp[threadIdx.x][ny]);
            gout[o]   = tg[threadIdx.x][ny];
            spkout[o] = ts[threadIdx.x][ny];
        }
    }
}

// ---------------- finalize: Out[t] = (g_gcol[t] . W) / N ----------------
__global__ void snn_finalize(const float* __restrict__ W, float* __restrict__ Out) {
    const int t = blockIdx.x;
    const int tid = threadIdx.x;
    __shared__ float sred[8];
    float acc = 0.0f;
    if (t > 0) {
        const float* gr = &g_gcol[(size_t)t * N_TOT];
        for (int n = tid; n < N_TOT; n += 256) acc += gr[n] * W[n];
    }
    #pragma unroll
    for (int off = 16; off > 0; off >>= 1) acc += __shfl_down_sync(0xffffffffu, acc, off);
    if ((tid & 31) == 0) sred[tid >> 5] = acc;
    __syncthreads();
    if (tid == 0) {
        float sm = 0.0f;
        #pragma unroll
        for (int ww = 0; ww < 8; ww++) sm += sred[ww];
        Out[t] = sm / 5000.0f;
    }
}

extern "C" void kernel_launch(void* const* d_in, const int* in_sizes, int n_in,
                              void* d_out, int out_size) {
    const float* dt    = (const float*)d_in[0];
    const float* Input = (const float*)d_in[1];
    const float* conn  = (const float*)d_in[2];
    const float* Wout  = (const float*)d_in[3];

    float* out = (float*)d_out;
    float* Out  = out;                       // [T]
    float* Vout = out + T_STEPS;             // [N, T]
    float* gout = Vout + (size_t)N_TOT * T_STEPS;
    float* spkout = gout + (size_t)N_TOT * T_STEPS;

    snn_reset<<<4, 256>>>();
    snn_spec<<<SBLK, STHR>>>(dt, Input);                  // sync-free speculation
    snn_transpose<<<296, dim3(32, 8)>>>(conn);            // gated grid-stride fallback prep
    snn_init<<<(N_TOT + 255) / 256, 256>>>();             // t=0 rows (+ fallback flags)
    snn_main<<<NBLK, NTHR>>>(dt, Input);                  // gated fallback
    {
        dim3 g((T_STEPS + 31) / 32, (N_TOT + 31) / 32);
        snn_post<<<g, dim3(32, 8)>>>(Vout, gout, spkout);
    }
    snn_finalize<<<T_STEPS, 256>>>(Wout, Out);
}